// round 8
// baseline (speedup 1.0000x reference)
#include <cuda_runtime.h>
#include <cstdint>

#define NB   8
#define CIN  256
#define HW   4096
#define CATT 128
#define COUT 256

// Scratch (device globals; no allocation allowed)
__device__ float g_feat[(size_t)NB * COUT * HW];   // [n][c][pos]
__device__ float g_attT[(size_t)NB * HW * CATT];   // [n][pos][c], tf32-rounded
__device__ float g_energy[(size_t)NB * HW * HW];   // [n][i][j] raw (pre-softmax)
__device__ float g_rmax[(size_t)NB * HW];          // row max
__device__ float g_rden[(size_t)NB * HW];          // row sum of exp(e - max)

// ===========================================================================
// Helpers — family-neutral PTX (sm_80+)
// ===========================================================================
__device__ __forceinline__ uint32_t smem_u32(const void* p) {
    uint32_t a;
    asm("{ .reg .u64 t; cvta.to.shared.u64 t, %1; cvt.u32.u64 %0, t; }" : "=r"(a) : "l"(p));
    return a;
}
__device__ __forceinline__ void mma_tf32(float c[4],
        uint32_t a0, uint32_t a1, uint32_t a2, uint32_t a3,
        uint32_t b0, uint32_t b1) {
    asm volatile("mma.sync.aligned.m16n8k8.row.col.f32.tf32.tf32.f32 "
                 "{%0,%1,%2,%3}, {%4,%5,%6,%7}, {%8,%9}, {%0,%1,%2,%3};"
                 : "+f"(c[0]), "+f"(c[1]), "+f"(c[2]), "+f"(c[3])
                 : "r"(a0), "r"(a1), "r"(a2), "r"(a3), "r"(b0), "r"(b1));
}
__device__ __forceinline__ float f2tf32f(float x) {
    uint32_t r; asm("cvt.rna.tf32.f32 %0, %1;" : "=r"(r) : "f"(x));
    return __uint_as_float(r);
}
#define CP16(dst, src) asm volatile("cp.async.ca.shared.global [%0], [%1], 16;" :: "r"(dst), "l"(src))
#define CP_COMMIT()    asm volatile("cp.async.commit_group;" ::: "memory")
#define CP_WAIT1()     asm volatile("cp.async.wait_group 1;" ::: "memory")
#define CP_WAIT0()     asm volatile("cp.async.wait_group 0;" ::: "memory")

// ===========================================================================
// Kernel 1: fused 1x1 conv + BN + ReLU for BOTH branches.
// grid.y: 0..3 -> feat (o0=y*64), 4..5 -> att (o0=(y-4)*64, tf32-rounded,
// stored transposed [pos][c]).  Tile 64(o) x 128(p), 2-stage cp.async.
// ===========================================================================
__global__ __launch_bounds__(256)
void conv_bn_relu_kernel(const float* __restrict__ x,
                         const float* __restrict__ reduc_w,
                         const float* __restrict__ reduc_gamma,
                         const float* __restrict__ reduc_beta,
                         const float* __restrict__ reduc_mean,
                         const float* __restrict__ reduc_var,
                         const float* __restrict__ att_w,
                         const float* __restrict__ att_gamma,
                         const float* __restrict__ att_beta,
                         const float* __restrict__ att_mean,
                         const float* __restrict__ att_var) {
    __shared__ float Ws[2][64][20];    // [m][k] padded
    __shared__ float Xs[2][16][132];   // [k][p] padded

    const int n  = blockIdx.z;
    const int p0 = blockIdx.x * 128;
    const bool isAtt = (blockIdx.y >= 4);
    const int o0 = (isAtt ? (blockIdx.y - 4) : blockIdx.y) * 64;
    const float* w     = isAtt ? att_w     : reduc_w;
    const float* gamma = isAtt ? att_gamma : reduc_gamma;
    const float* beta  = isAtt ? att_beta  : reduc_beta;
    const float* mean  = isAtt ? att_mean  : reduc_mean;
    const float* var   = isAtt ? att_var   : reduc_var;

    const int tid = threadIdx.x;
    const int tx = tid & 15, ty = tid >> 4;
    const float* X = x + (size_t)n * CIN * HW;

    auto load_stage = [&](int s, int k0) {
        {
            int m = tid >> 2, k4 = tid & 3;
            CP16(smem_u32(&Ws[s][m][k4 * 4]), w + (size_t)(o0 + m) * CIN + k0 + k4 * 4);
        }
        #pragma unroll
        for (int i = tid; i < 512; i += 256) {
            int k = i >> 5, p4 = i & 31;
            CP16(smem_u32(&Xs[s][k][p4 * 4]), X + (size_t)(k0 + k) * HW + p0 + p4 * 4);
        }
        CP_COMMIT();
    };

    float acc[4][8] = {};
    load_stage(0, 0);
    load_stage(1, 16);

    for (int ks = 0; ks < 16; ks++) {
        CP_WAIT1();
        __syncthreads();
        const int s = ks & 1;
        #pragma unroll
        for (int k = 0; k < 16; k++) {
            float a[4];
            #pragma unroll
            for (int i = 0; i < 4; i++) a[i] = Ws[s][ty * 4 + i][k];
            float4 b0 = *(const float4*)&Xs[s][k][tx * 8];
            float4 b1 = *(const float4*)&Xs[s][k][tx * 8 + 4];
            float b[8] = {b0.x, b0.y, b0.z, b0.w, b1.x, b1.y, b1.z, b1.w};
            #pragma unroll
            for (int i = 0; i < 4; i++)
                #pragma unroll
                for (int j = 0; j < 8; j++)
                    acc[i][j] = fmaf(a[i], b[j], acc[i][j]);
        }
        __syncthreads();
        if (ks + 2 < 16) load_stage(s, (ks + 2) * 16);
        else CP_COMMIT();
    }
    CP_WAIT0();

    float v[4][8];
    #pragma unroll
    for (int i = 0; i < 4; i++) {
        int o = o0 + ty * 4 + i;
        float inv  = gamma[o] * rsqrtf(var[o] + 1e-5f);
        float bias = beta[o] - mean[o] * inv;
        #pragma unroll
        for (int j = 0; j < 8; j++)
            v[i][j] = fmaxf(acc[i][j] * inv + bias, 0.0f);
    }
    if (isAtt) {
        // tf32(rna)-round once here; energy MMA then consumes exact tf32 values.
        #pragma unroll
        for (int j = 0; j < 8; j++) {
            int p = p0 + tx * 8 + j;
            float4 q = make_float4(f2tf32f(v[0][j]), f2tf32f(v[1][j]),
                                   f2tf32f(v[2][j]), f2tf32f(v[3][j]));
            *(float4*)&g_attT[((size_t)n * HW + p) * CATT + o0 + ty * 4] = q;
        }
    } else {
        #pragma unroll
        for (int i = 0; i < 4; i++) {
            int o = o0 + ty * 4 + i;
            float* dst = &g_feat[((size_t)n * COUT + o) * HW + p0 + tx * 8];
            *(float4*)dst       = make_float4(v[i][0], v[i][1], v[i][2], v[i][3]);
            *(float4*)(dst + 4) = make_float4(v[i][4], v[i][5], v[i][6], v[i][7]);
        }
    }
}

// ===========================================================================
// Kernel 2: energy + online softmax stats.
// CTA owns i-stripe [i0, i0+128); loops all 32 j-tiles (128 wide).
// A (i-tile) resident; B double-buffered cp.async; per-tile epilogue staged
// through the consumed B buffer; online row max/denominator accumulated.
// 8 warps, warp tile 64(M) x 32(N).
// SMEM: A @0 (67584B), B0 @67584, B1 @135168. Total 202752B.
// ===========================================================================
#define E_LD 132
#define E_TILEB (128 * E_LD * 4)     // 67584
#define E_SMEM  (3 * E_TILEB)        // 202752

__global__ __launch_bounds__(256, 1)
void energy_fused_kernel(const float* __restrict__ mask) {
    extern __shared__ float sm[];
    float* As = sm;

    const int tid  = threadIdx.x;
    const int wid  = tid >> 5, lane = tid & 31;
    const int n  = blockIdx.y;
    const int i0 = blockIdx.x * 128;
    const float* attn = g_attT + (size_t)n * HW * CATT;

    // A fill (group 0)
    #pragma unroll
    for (int idx = tid; idx < 4096; idx += 256) {
        int row = idx >> 5, ch = idx & 31;
        CP16(smem_u32(&As[row * E_LD + ch * 4]),
             attn + (size_t)(i0 + row) * CATT + ch * 4);
    }
    CP_COMMIT();

    auto fill_B = [&](int buf, int jt) {
        float* B = sm + (1 + buf) * 128 * E_LD;
        int j0 = jt * 128;
        #pragma unroll
        for (int idx = tid; idx < 4096; idx += 256) {
            int row = idx >> 5, ch = idx & 31;
            CP16(smem_u32(&B[row * E_LD + ch * 4]),
                 attn + (size_t)(j0 + row) * CATT + ch * 4);
        }
        CP_COMMIT();
    };
    fill_B(0, 0);
    fill_B(1, 1);

    const int wm = wid & 1, wn = wid >> 1;     // M half, N quarter
    const int r = lane >> 2, kq = lane & 3;
    const float inv_s = 0.08838834764831845f;  // 1/(1e-8+sqrt(128))

    float Mreg[16], Dreg[16];
    #pragma unroll
    for (int k = 0; k < 16; k++) { Mreg[k] = -1e30f; Dreg[k] = 0.0f; }

    for (int t = 0; t < 32; t++) {
        CP_WAIT1();
        __syncthreads();
        float* Bs = sm + (1 + (t & 1)) * 128 * E_LD;

        float cc[4][4][4] = {};
        #pragma unroll 2
        for (int ks = 0; ks < 16; ks++) {
            const int k8 = ks * 8;
            uint32_t af[4][4], bf[4][2];
            #pragma unroll
            for (int mt = 0; mt < 4; mt++) {
                int mb = wm * 64 + mt * 16;
                af[mt][0] = __float_as_uint(As[(mb + r) * E_LD + k8 + kq]);
                af[mt][1] = __float_as_uint(As[(mb + r + 8) * E_LD + k8 + kq]);
                af[mt][2] = __float_as_uint(As[(mb + r) * E_LD + k8 + kq + 4]);
                af[mt][3] = __float_as_uint(As[(mb + r + 8) * E_LD + k8 + kq + 4]);
            }
            #pragma unroll
            for (int nt = 0; nt < 4; nt++) {
                int nb = wn * 32 + nt * 8;
                bf[nt][0] = __float_as_uint(Bs[(nb + r) * E_LD + k8 + kq]);
                bf[nt][1] = __float_as_uint(Bs[(nb + r) * E_LD + k8 + kq + 4]);
            }
            #pragma unroll
            for (int mt = 0; mt < 4; mt++)
                #pragma unroll
                for (int nt = 0; nt < 4; nt++)
                    mma_tf32(cc[mt][nt], af[mt][0], af[mt][1], af[mt][2], af[mt][3],
                             bf[nt][0], bf[nt][1]);
        }
        __syncthreads();           // MMA reads of Bs done before C staging

        // Stage C into Bs: S[i_local][j_local], stride E_LD
        #pragma unroll
        for (int mt = 0; mt < 4; mt++) {
            int ib = wm * 64 + mt * 16 + r;
            #pragma unroll
            for (int nt = 0; nt < 4; nt++) {
                int jb = wn * 32 + nt * 8 + kq * 2;
                Bs[ib * E_LD + jb]           = cc[mt][nt][0];
                Bs[ib * E_LD + jb + 1]       = cc[mt][nt][1];
                Bs[(ib + 8) * E_LD + jb]     = cc[mt][nt][2];
                Bs[(ib + 8) * E_LD + jb + 1] = cc[mt][nt][3];
            }
        }
        __syncthreads();

        // Scale + mask, store raw E, accumulate online row max/denominator.
        const int j0 = t * 128;
        #pragma unroll
        for (int k = 0; k < 16; k++) {
            const int row = k * 8 + wid;     // warp-uniform row
            float4 e = *(const float4*)&Bs[row * E_LD + lane * 4];
            float4 mm = *(const float4*)&mask[(size_t)n * HW + j0 + lane * 4];
            e.x = e.x * inv_s + (mm.x - 1.0f) * 1e8f;
            e.y = e.y * inv_s + (mm.y - 1.0f) * 1e8f;
            e.z = e.z * inv_s + (mm.z - 1.0f) * 1e8f;
            e.w = e.w * inv_s + (mm.w - 1.0f) * 1e8f;
            *(float4*)&g_energy[((size_t)n * HW + i0 + row) * HW + j0 + lane * 4] = e;

            float m = fmaxf(fmaxf(e.x, e.y), fmaxf(e.z, e.w));
            #pragma unroll
            for (int o = 16; o > 0; o >>= 1)
                m = fmaxf(m, __shfl_xor_sync(0xffffffffu, m, o));
            float s = __expf(e.x - m) + __expf(e.y - m) + __expf(e.z - m) + __expf(e.w - m);
            #pragma unroll
            for (int o = 16; o > 0; o >>= 1)
                s += __shfl_xor_sync(0xffffffffu, s, o);
            float Mo = Mreg[k];
            float Mn = fmaxf(Mo, m);
            Dreg[k] = Dreg[k] * __expf(Mo - Mn) + s * __expf(m - Mn);
            Mreg[k] = Mn;
        }
        __syncthreads();           // reads of Bs done before prefetch overwrites

        if (t + 2 < 32) fill_B(t & 1, t + 2);
        else CP_COMMIT();
    }

    if (lane == 0) {
        #pragma unroll
        for (int k = 0; k < 16; k++) {
            size_t gi = (size_t)n * HW + i0 + k * 8 + wid;
            g_rmax[gi] = Mreg[k];
            g_rden[gi] = Dreg[k];
        }
    }
}

// ===========================================================================
// Kernel 3: out = softmax(E) @ feat^T, fused normalize.
// A stage (raw E) transformed in place: w = exp(e - M[i]) * (1/D[i]).
// CTA: M=128(i) x N=256(c), K=4096, Kt=32, 3-stage cp.async.
// ===========================================================================
#define O_LD 36
#define O_STAGE ((128 + 256) * O_LD * 4)  // 55296 B
#define O_SMEM  (3 * O_STAGE)             // 165888 B
#define O_NIT   128

__global__ __launch_bounds__(256, 1)
void out_mma_kernel(const float* __restrict__ mask, float* __restrict__ out) {
    extern __shared__ char smc[];
    __shared__ float Ms[128], Di[128];
    const uint32_t sb = smem_u32(smc);
    const int tid  = threadIdx.x;
    const int wid  = tid >> 5, lane = tid & 31;
    const int n  = blockIdx.y;
    const int i0 = blockIdx.x * 128;
    const float* Wg = g_energy + (size_t)n * HW * HW;     // [i][j] raw
    const float* F  = g_feat   + (size_t)n * COUT * HW;   // [c][j]

    if (tid < 128) {
        Ms[tid] = g_rmax[(size_t)n * HW + i0 + tid];
        Di[tid] = 1.0f / g_rden[(size_t)n * HW + i0 + tid];
    }

    auto load_stage = [&](int s, int kt) {
        uint32_t base = sb + (uint32_t)s * O_STAGE;
        #pragma unroll
        for (int idx = tid; idx < 3072; idx += 256) {
            if (idx < 1024) {
                int row = idx >> 3, ch = idx & 7;
                CP16(base + row * 144 + ch * 16,
                     Wg + (size_t)(i0 + row) * HW + kt + ch * 4);
            } else {
                int q = idx - 1024;
                int row = q >> 3, ch = q & 7;
                CP16(base + 18432 + row * 144 + ch * 16,
                     F + (size_t)row * HW + kt + ch * 4);
            }
        }
        CP_COMMIT();
    };

    load_stage(0, 0);
    load_stage(1, 32);

    const int wm = wid & 1, wn = wid >> 1;
    const int r = lane >> 2, kq = lane & 3;
    float cc[4][8][4] = {};

    for (int it = 0; it < O_NIT; ++it) {
        CP_WAIT1();
        __syncthreads();
        float* Ap = (float*)(smc + (it % 3) * O_STAGE);

        // In-place softmax transform of the A (energy) part of this stage.
        #pragma unroll
        for (int idx = tid; idx < 1024; idx += 256) {
            int row = idx >> 3, ch = idx & 7;
            float4 v = *(const float4*)&Ap[row * O_LD + ch * 4];
            float M = Ms[row], d = Di[row];
            v.x = __expf(v.x - M) * d;
            v.y = __expf(v.y - M) * d;
            v.z = __expf(v.z - M) * d;
            v.w = __expf(v.w - M) * d;
            *(float4*)&Ap[row * O_LD + ch * 4] = v;
        }
        __syncthreads();

        const float* As = Ap;
        const float* Bs = Ap + 128 * O_LD;
        #pragma unroll
        for (int ks = 0; ks < 4; ks++) {
            const int k8 = ks * 8;
            uint32_t af[4][4];
            #pragma unroll
            for (int mt = 0; mt < 4; mt++) {
                int mb = wm * 64 + mt * 16;
                af[mt][0] = __float_as_uint(As[(mb + r) * O_LD + k8 + kq]);
                af[mt][1] = __float_as_uint(As[(mb + r + 8) * O_LD + k8 + kq]);
                af[mt][2] = __float_as_uint(As[(mb + r) * O_LD + k8 + kq + 4]);
                af[mt][3] = __float_as_uint(As[(mb + r + 8) * O_LD + k8 + kq + 4]);
            }
            #pragma unroll
            for (int nt = 0; nt < 8; nt++) {
                int nb = wn * 64 + nt * 8;
                uint32_t b0 = __float_as_uint(Bs[(nb + r) * O_LD + k8 + kq]);
                uint32_t b1 = __float_as_uint(Bs[(nb + r) * O_LD + k8 + kq + 4]);
                #pragma unroll
                for (int mt = 0; mt < 4; mt++)
                    mma_tf32(cc[mt][nt], af[mt][0], af[mt][1], af[mt][2], af[mt][3], b0, b1);
            }
        }
        __syncthreads();
        if (it + 2 < O_NIT) load_stage((it + 2) % 3, (it + 2) * 32);
        else CP_COMMIT();
    }
    CP_WAIT0();
    __syncthreads();

    // Stage C: S[c_local][i_local], stride 132.
    float* S = (float*)smc;
    #pragma unroll
    for (int mt = 0; mt < 4; mt++) {
        int ib = wm * 64 + mt * 16 + r;
        #pragma unroll
        for (int nt = 0; nt < 8; nt++) {
            int cb = wn * 64 + nt * 8 + kq * 2;
            S[cb * 132 + ib]           = cc[mt][nt][0];
            S[(cb + 1) * 132 + ib]     = cc[mt][nt][1];
            S[cb * 132 + ib + 8]       = cc[mt][nt][2];
            S[(cb + 1) * 132 + ib + 8] = cc[mt][nt][3];
        }
    }
    __syncthreads();

    #pragma unroll 4
    for (int idx = tid; idx < 8192; idx += 256) {
        int row = idx >> 5, ch = idx & 31;
        int ii = i0 + ch * 4;
        float4 v = *(const float4*)&S[row * 132 + ch * 4];
        float4 mm = *(const float4*)&mask[(size_t)n * HW + ii];
        v.x *= mm.x; v.y *= mm.y; v.z *= mm.z; v.w *= mm.w;
        *(float4*)&out[((size_t)n * COUT + row) * HW + ii] = v;
    }
}

// ===========================================================================
extern "C" void kernel_launch(void* const* d_in, const int* in_sizes, int n_in,
                              void* d_out, int out_size) {
    const float* x           = (const float*)d_in[0];
    const float* mask        = (const float*)d_in[1];
    const float* reduc_w     = (const float*)d_in[2];
    const float* reduc_gamma = (const float*)d_in[3];
    const float* reduc_beta  = (const float*)d_in[4];
    const float* reduc_mean  = (const float*)d_in[5];
    const float* reduc_var   = (const float*)d_in[6];
    const float* att_w       = (const float*)d_in[7];
    const float* att_gamma   = (const float*)d_in[8];
    const float* att_beta    = (const float*)d_in[9];
    const float* att_mean    = (const float*)d_in[10];
    const float* att_var     = (const float*)d_in[11];
    float* out = (float*)d_out;

    cudaFuncSetAttribute(energy_fused_kernel, cudaFuncAttributeMaxDynamicSharedMemorySize, E_SMEM);
    cudaFuncSetAttribute(out_mma_kernel,      cudaFuncAttributeMaxDynamicSharedMemorySize, O_SMEM);

    conv_bn_relu_kernel<<<dim3(HW / 128, 6, NB), 256>>>(
        x, reduc_w, reduc_gamma, reduc_beta, reduc_mean, reduc_var,
        att_w, att_gamma, att_beta, att_mean, att_var);

    energy_fused_kernel<<<dim3(HW / 128, NB), 256, E_SMEM>>>(mask);

    out_mma_kernel<<<dim3(HW / 128, NB), 256, O_SMEM>>>(mask, out);
}